// round 8
// baseline (speedup 1.0000x reference)
#include <cuda_runtime.h>
#include <cuda_bf16.h>
#include <cstdint>
#include <cstddef>

#define BATCH 16384
#define DG    256

// SMEM geometry: A in fragment-order bf16 planes (hi at 0, lo at +APLANE).
// Chunk(mb 0..7, kb 0..15, lane 0..31) = 16B: lane's m16k16 A fragment.
#define APLANE    65536
#define SA_BYTES  (2 * APLANE)                     // 131,072
#define SB_PLANE  16384                            // one K32 chunk, one plane (bytes)
#define SB_BUF    (2 * SB_PLANE)                   // hi+lo per chunk = 32,768
#define NSTAGE    3
#define SB_BYTES  (NSTAGE * SB_BUF)                // 98,304 (3-stage ring)
#define SMEM_TOTAL (SA_BYTES + SB_BYTES)           // 229,376

#define NTHREADS  512

// Packed 256x256 weight block: hi plane [kb16][p16][lane32][8 bf16], lo at +65536.
#define BLK_STRIDE 131072                          // bf16 elems per packed block

// ===========================================================================
// Global scratch (__device__ globals: allocation-free rule)
// ===========================================================================
__device__ float g_bufs[9][BATCH * DG];
__device__ float l_bufs[10][BATCH * DG];
__device__ __align__(128) __nv_bfloat16 WT_eq[BLK_STRIDE];
__device__ __align__(128) __nv_bfloat16 WT_tr[BLK_STRIDE];
__device__ __align__(128) __nv_bfloat16 WT_ab[BLK_STRIDE];
__device__ __align__(128) __nv_bfloat16 WT_ge[2 * BLK_STRIDE];   // K=512: 2 K-half blocks
__device__ __align__(128) __nv_bfloat16 WT_1 [2 * BLK_STRIDE];   // K=512: 2 K-half blocks
__device__ __align__(128) __nv_bfloat16 WT_2 [4 * BLK_STRIDE];   // N=1024: 4 N-tile blocks

__device__ __forceinline__ float sigm(float x) { return 1.0f / (1.0f + expf(-x)); }

__device__ __forceinline__ uint32_t smem_to_u32(const void* p) {
    uint32_t a;
    asm("{ .reg .u64 t; cvta.to.shared.u64 t, %1; cvt.u32.u64 %0, t; }" : "=r"(a) : "l"(p));
    return a;
}

#define CP_ASYNC16(dst_u32, src_ptr) \
    asm volatile("cp.async.cg.shared.global [%0], [%1], 16;" :: "r"(dst_u32), "l"(src_ptr))
#define CP_COMMIT() asm volatile("cp.async.commit_group;" ::: "memory")
#define CP_WAIT1()  asm volatile("cp.async.wait_group 1;" ::: "memory")
#define CP_WAIT0()  asm volatile("cp.async.wait_group 0;" ::: "memory")

#define LDS128(r0, r1, r2, r3, addr) \
    asm volatile("ld.shared.v4.b32 {%0,%1,%2,%3}, [%4];" \
        : "=r"(r0), "=r"(r1), "=r"(r2), "=r"(r3) : "r"(addr))

#define MMA16816(d, a0, a1, a2, a3, b0, b1) \
    asm volatile("mma.sync.aligned.m16n8k16.row.col.f32.bf16.bf16.f32 " \
        "{%0,%1,%2,%3}, {%4,%5,%6,%7}, {%8,%9}, {%0,%1,%2,%3};" \
        : "+f"((d)[0]), "+f"((d)[1]), "+f"((d)[2]), "+f"((d)[3]) \
        : "r"(a0), "r"(a1), "r"(a2), "r"(a3), "r"(b0), "r"(b1))

__device__ __forceinline__ void split2(float2 x, uint32_t& h, uint32_t& l) {
    __nv_bfloat162 hp = __float22bfloat162_rn(x);
    float2 hf = __bfloat1622float2(hp);
    float2 r = make_float2(x.x - hf.x, x.y - hf.y);
    __nv_bfloat162 lp = __float22bfloat162_rn(r);
    h = *reinterpret_cast<uint32_t*>(&hp);
    l = *reinterpret_cast<uint32_t*>(&lp);
}

// Write one A fragment chunk (16B hi + 16B lo) from 8 fp32 values:
// e* = even-nt acc (k-low half), o* = odd-nt acc (k-high half).
__device__ __forceinline__ void write_A_frag(char* sA, int mb, int kb, int lane,
                                             float e0, float e1, float e2, float e3,
                                             float o0, float o1, float o2, float o3) {
    uint32_t h0, l0, h1, l1, h2, l2, h3, l3;
    split2(make_float2(e0, e1), h0, l0);
    split2(make_float2(e2, e3), h1, l1);
    split2(make_float2(o0, o1), h2, l2);
    split2(make_float2(o2, o3), h3, l3);
    uint32_t off = (uint32_t)((mb * 16 + kb) * 32 + lane) * 16;
    *(uint4*)(sA + off) = make_uint4(h0, h1, h2, h3);
    *(uint4*)(sA + APLANE + off) = make_uint4(l0, l1, l2, l3);
}

// ===========================================================================
// prep: pack weights into fragment-order blocks.
// ===========================================================================
__device__ __forceinline__ void pack_store(__nv_bfloat16* dst, int k, int n, float w) {
    int kb = k >> 4;
    int p = n >> 4;
    int lane = (n & 7) * 4 + ((k >> 1) & 3);
    int idx = ((n >> 3) & 1) * 4 + ((k >> 3) & 1) * 2 + (k & 1);
    size_t off = ((size_t)((kb * 16 + p) * 32 + lane)) * 8 + idx;
    __nv_bfloat16 h = __float2bfloat16(w);
    dst[off] = h;
    dst[65536 + off] = __float2bfloat16(w - __bfloat162float(h));
}

__global__ void prep_kernel(const float* __restrict__ Wge, const float* __restrict__ Weq,
                            const float* __restrict__ Wtr, const float* __restrict__ Wab,
                            const float* __restrict__ W1,  const float* __restrict__ W2) {
    int i0 = blockIdx.x * 256 + threadIdx.x;
    int stride = gridDim.x * 256;
    for (int i = i0; i < 11 * 65536; i += stride) {
        int blk = i >> 16, e = i & 65535;
        int k = e >> 8, n = e & 255;
        float w;
        __nv_bfloat16* dst;
        if (blk == 0)      { w = Weq[k * 256 + n]; dst = WT_eq; }
        else if (blk == 1) { w = Wtr[k * 256 + n]; dst = WT_tr; }
        else if (blk == 2) { w = Wab[k * 256 + n]; dst = WT_ab; }
        else if (blk <= 4) { int h = blk - 3; w = Wge[(k + h * 256) * 256 + n]; dst = WT_ge + (size_t)h * BLK_STRIDE; }
        else if (blk <= 6) { int h = blk - 5; w = W1 [(k + h * 256) * 256 + n]; dst = WT_1  + (size_t)h * BLK_STRIDE; }
        else               { int t = blk - 7; int ng = t * 256 + n;
                             w = (ng < 1000) ? W2[k * 1000 + ng] : 0.0f;
                             dst = WT_2 + (size_t)t * BLK_STRIDE; }
        pack_store(dst, k, n, w);
    }
}

// ===========================================================================
// B chunk streaming (K=32 per chunk) via cp.async. 512 threads.
// ===========================================================================
__device__ __forceinline__ void issue_chunk(uint32_t sB, int buf,
                                            const __nv_bfloat16* __restrict__ blk,
                                            int kc, int tid) {
    uint32_t dst = sB + (uint32_t)buf * SB_BUF;
    const __nv_bfloat16* hi = blk + kc * 8192;
    const __nv_bfloat16* lo = blk + 65536 + kc * 8192;
#pragma unroll
    for (int j = 0; j < 2; j++) {
        int e = j * NTHREADS + tid;
        CP_ASYNC16(dst + e * 16, hi + e * 8);
    }
#pragma unroll
    for (int j = 0; j < 2; j++) {
        int e = j * NTHREADS + tid;
        CP_ASYNC16(dst + SB_PLANE + e * 16, lo + e * 8);
    }
}

// ===========================================================================
// HMMA GEMM core: acc[2][8][4] += A(frag planes) @ block^T (bf16x3 split)
// 16 warps: wm (0..3) x wn (0..3); warp tile m32 x n64.
// 3-stage cp.async ring, ONE __syncthreads per K-chunk.
// Ends with __syncthreads (safe to write sA right after).
// ===========================================================================
__device__ __forceinline__ void hmma_gemm_k256(uint32_t sA, uint32_t sB,
                                               const __nv_bfloat16* __restrict__ blk,
                                               float acc[2][8][4],
                                               int tid, bool zero_acc) {
    if (zero_acc) {
#pragma unroll
        for (int mt = 0; mt < 2; mt++)
#pragma unroll
            for (int nt = 0; nt < 8; nt++)
#pragma unroll
                for (int i = 0; i < 4; i++) acc[mt][nt][i] = 0.f;
    }
    const int lane = tid & 31;
    const int wm = (tid >> 5) & 3, wn = tid >> 7;
    // A fragment base for this warp (mb = wm*2 + mt)
    const uint32_t abase = sA + (uint32_t)(wm * 2 * 8192 + lane * 16);

    issue_chunk(sB, 0, blk, 0, tid);
    CP_COMMIT();
    issue_chunk(sB, 1, blk, 1, tid);
    CP_COMMIT();

    int buf = 0;        // buffer holding chunk kc
    int nbuf = 2;       // next buffer to fill (chunk kc+2)
    for (int kc = 0; kc < 8; kc++) {
        if (kc == 7) { CP_WAIT0(); } else { CP_WAIT1(); }
        __syncthreads();
        if (kc + 2 < 8) {
            issue_chunk(sB, nbuf, blk, kc + 2, tid);
            CP_COMMIT();
        }
        uint32_t sbuf = sB + (uint32_t)buf * SB_BUF;
        buf = (buf == NSTAGE - 1) ? 0 : buf + 1;
        nbuf = (nbuf == NSTAGE - 1) ? 0 : nbuf + 1;
#pragma unroll
        for (int kt = 0; kt < 2; kt++) {
            const int kb = kc * 2 + kt;
            uint32_t ah[2][4], al[2][4];
#pragma unroll
            for (int mt = 0; mt < 2; mt++) {
                uint32_t aaddr = abase + (uint32_t)(mt * 8192 + kb * 512);
                LDS128(ah[mt][0], ah[mt][1], ah[mt][2], ah[mt][3], aaddr);
                LDS128(al[mt][0], al[mt][1], al[mt][2], al[mt][3], aaddr + APLANE);
            }
#pragma unroll
            for (int ntp = 0; ntp < 4; ntp++) {
                uint32_t ba = sbuf + (uint32_t)((kt * 16 + wn * 4 + ntp) * 512 + lane * 16);
                uint32_t h0, h1, h2, h3, l0, l1, l2, l3;
                LDS128(h0, h1, h2, h3, ba);
                LDS128(l0, l1, l2, l3, ba + SB_PLANE);
                float* aE0 = acc[0][2 * ntp];
                float* aO0 = acc[0][2 * ntp + 1];
                float* aE1 = acc[1][2 * ntp];
                float* aO1 = acc[1][2 * ntp + 1];
                // product hh
                MMA16816(aE0, ah[0][0], ah[0][1], ah[0][2], ah[0][3], h0, h1);
                MMA16816(aO0, ah[0][0], ah[0][1], ah[0][2], ah[0][3], h2, h3);
                MMA16816(aE1, ah[1][0], ah[1][1], ah[1][2], ah[1][3], h0, h1);
                MMA16816(aO1, ah[1][0], ah[1][1], ah[1][2], ah[1][3], h2, h3);
                // product hl
                MMA16816(aE0, ah[0][0], ah[0][1], ah[0][2], ah[0][3], l0, l1);
                MMA16816(aO0, ah[0][0], ah[0][1], ah[0][2], ah[0][3], l2, l3);
                MMA16816(aE1, ah[1][0], ah[1][1], ah[1][2], ah[1][3], l0, l1);
                MMA16816(aO1, ah[1][0], ah[1][1], ah[1][2], ah[1][3], l2, l3);
                // product lh
                MMA16816(aE0, al[0][0], al[0][1], al[0][2], al[0][3], h0, h1);
                MMA16816(aO0, al[0][0], al[0][1], al[0][2], al[0][3], h2, h3);
                MMA16816(aE1, al[1][0], al[1][1], al[1][2], al[1][3], h0, h1);
                MMA16816(aO1, al[1][0], al[1][1], al[1][2], al[1][3], h2, h3);
            }
        }
    }
    __syncthreads();
}

// Fill A fragment planes (128 x 256) from row-major gmem. 512 threads.
__device__ __forceinline__ void fill_A_frag(char* sA, const float* __restrict__ src,
                                            int ld, int tid) {
#pragma unroll
    for (int i = 0; i < 8; i++) {
        int idx = i * NTHREADS + tid;           // 0..4095 = (mb*16+kb)*32+lane
        int mb = idx >> 9, kb = (idx >> 5) & 15, ln = idx & 31;
        int gid = ln >> 2, qid = ln & 3;
        const float* p0 = src + (size_t)(mb * 16 + gid) * ld + kb * 16 + 2 * qid;
        float2 x0 = *(const float2*)(p0);                 // row gid,   k low
        float2 x1 = *(const float2*)(p0 + 8 * (size_t)ld);// row gid+8, k low
        float2 x2 = *(const float2*)(p0 + 8);             // row gid,   k high
        float2 x3 = *(const float2*)(p0 + 8 * (size_t)ld + 8);
        write_A_frag(sA, mb, kb, ln, x0.x, x0.y, x1.x, x1.y, x2.x, x2.y, x3.x, x3.y);
    }
}

// Per-fragment index helper (16 warps: wm 0..3, wn 0..3)
#define FRAG_SETUP() \
    const int lane = tid & 31; \
    const int wm = (tid >> 5) & 3, wn = tid >> 7; \
    const int gid = lane >> 2, qid = lane & 3;

// ===========================================================================
// Fused plate kernel (HMMA): 128 rows per CTA, 512 threads.
// ===========================================================================
template <bool DESC>
__global__ __launch_bounds__(NTHREADS, 1) void plate_hmma(
    const float* __restrict__ g_in, const float* __restrict__ l_in,
    float* __restrict__ out,
    const float* __restrict__ b_eq, const float* __restrict__ b_tr,
    const float* __restrict__ b_ab, const float* __restrict__ alpha_p) {
    extern __shared__ char sm[];
    char* sA_p = sm;
    uint32_t sA = smem_to_u32(sm);
    uint32_t sB = sA + SA_BYTES;
    const int tid = threadIdx.x;
    const size_t rowbase = (size_t)blockIdx.x * 128;
    FRAG_SETUP();

    fill_A_frag(sA_p, l_in + rowbase * 256, 256, tid);

    float acc[2][8][4];
    // GEMM 1: l @ W_eq
    hmma_gemm_k256(sA, sB, WT_eq, acc, tid, true);

    // Epilogue 1: df = g - sigmoid(acc + b_eq) -> A fragment planes
#pragma unroll
    for (int mt = 0; mt < 2; mt++) {
#pragma unroll
        for (int ntp = 0; ntp < 4; ntp++) {
            int ce = wn * 64 + ntp * 16 + qid * 2;
            int r = wm * 32 + mt * 16 + gid;
            size_t ro = (rowbase + r) * 256;
            float2 beE = *(const float2*)(b_eq + ce);
            float2 beO = *(const float2*)(b_eq + ce + 8);
            float2 gE0 = *(const float2*)(g_in + ro + ce);
            float2 gE1 = *(const float2*)(g_in + ro + 8 * 256 + ce);
            float2 gO0 = *(const float2*)(g_in + ro + ce + 8);
            float2 gO1 = *(const float2*)(g_in + ro + 8 * 256 + ce + 8);
            const float* aE = acc[mt][2 * ntp];
            const float* aO = acc[mt][2 * ntp + 1];
            write_A_frag(sA_p, wm * 2 + mt, wn * 4 + ntp, lane,
                         gE0.x - sigm(aE[0] + beE.x), gE0.y - sigm(aE[1] + beE.y),
                         gE1.x - sigm(aE[2] + beE.x), gE1.y - sigm(aE[3] + beE.y),
                         gO0.x - sigm(aO[0] + beO.x), gO0.y - sigm(aO[1] + beO.y),
                         gO1.x - sigm(aO[2] + beO.x), gO1.y - sigm(aO[3] + beO.y));
        }
    }

    // GEMM 2: df @ W_tr
    hmma_gemm_k256(sA, sB, WT_tr, acc, tid, true);

    const float alpha = *alpha_p;

    if (!DESC) {
        // out = g - alpha*(acc + b_tr)
#pragma unroll
        for (int mt = 0; mt < 2; mt++) {
#pragma unroll
            for (int nt = 0; nt < 8; nt++) {
                int col = wn * 64 + nt * 8 + qid * 2;
                int r = wm * 32 + mt * 16 + gid;
                size_t ro = (rowbase + r) * 256 + col;
                float2 bt = *(const float2*)(b_tr + col);
                float2 g0 = *(const float2*)(g_in + ro);
                float2 g1 = *(const float2*)(g_in + ro + 8 * 256);
                float2 o0, o1;
                o0.x = g0.x - alpha * (acc[mt][nt][0] + bt.x);
                o0.y = g0.y - alpha * (acc[mt][nt][1] + bt.y);
                o1.x = g1.x - alpha * (acc[mt][nt][2] + bt.x);
                o1.y = g1.y - alpha * (acc[mt][nt][3] + bt.y);
                *(float2*)(out + ro) = o0;
                *(float2*)(out + ro + 8 * 256) = o1;
            }
        }
    } else {
        // delta = alpha*(acc + b_tr) -> A fragment planes
#pragma unroll
        for (int mt = 0; mt < 2; mt++) {
#pragma unroll
            for (int ntp = 0; ntp < 4; ntp++) {
                int ce = wn * 64 + ntp * 16 + qid * 2;
                float2 btE = *(const float2*)(b_tr + ce);
                float2 btO = *(const float2*)(b_tr + ce + 8);
                const float* aE = acc[mt][2 * ntp];
                const float* aO = acc[mt][2 * ntp + 1];
                write_A_frag(sA_p, wm * 2 + mt, wn * 4 + ntp, lane,
                             alpha * (aE[0] + btE.x), alpha * (aE[1] + btE.y),
                             alpha * (aE[2] + btE.x), alpha * (aE[3] + btE.y),
                             alpha * (aO[0] + btO.x), alpha * (aO[1] + btO.y),
                             alpha * (aO[2] + btO.x), alpha * (aO[3] + btO.y));
            }
        }

        // GEMM 3: delta @ W_ab
        hmma_gemm_k256(sA, sB, WT_ab, acc, tid, true);

        // out = l + acc + b_ab
#pragma unroll
        for (int mt = 0; mt < 2; mt++) {
#pragma unroll
            for (int nt = 0; nt < 8; nt++) {
                int col = wn * 64 + nt * 8 + qid * 2;
                int r = wm * 32 + mt * 16 + gid;
                size_t ro = (rowbase + r) * 256 + col;
                float2 ba = *(const float2*)(b_ab + col);
                float2 l0 = *(const float2*)(l_in + ro);
                float2 l1 = *(const float2*)(l_in + ro + 8 * 256);
                float2 o0, o1;
                o0.x = l0.x + acc[mt][nt][0] + ba.x;
                o0.y = l0.y + acc[mt][nt][1] + ba.y;
                o1.x = l1.x + acc[mt][nt][2] + ba.x;
                o1.y = l1.y + acc[mt][nt][3] + ba.y;
                *(float2*)(out + ro) = o0;
                *(float2*)(out + ro + 8 * 256) = o1;
            }
        }
    }
}

// ===========================================================================
// Encoder: g0 = relu(x @ W_ge + b_ge), K = 512 as two accumulated K=256 passes
// ===========================================================================
__global__ __launch_bounds__(NTHREADS, 1) void encoder_hmma(
    const float* __restrict__ x, const float* __restrict__ b_ge,
    float* __restrict__ g0) {
    extern __shared__ char sm[];
    char* sA_p = sm;
    uint32_t sA = smem_to_u32(sm);
    uint32_t sB = sA + SA_BYTES;
    const int tid = threadIdx.x;
    const size_t rowbase = (size_t)blockIdx.x * 128;
    FRAG_SETUP();

    float acc[2][8][4];
    fill_A_frag(sA_p, x + rowbase * 512, 512, tid);
    hmma_gemm_k256(sA, sB, WT_ge, acc, tid, true);
    fill_A_frag(sA_p, x + rowbase * 512 + 256, 512, tid);
    hmma_gemm_k256(sA, sB, WT_ge + BLK_STRIDE, acc, tid, false);

#pragma unroll
    for (int mt = 0; mt < 2; mt++) {
#pragma unroll
        for (int nt = 0; nt < 8; nt++) {
            int col = wn * 64 + nt * 8 + qid * 2;
            int r = wm * 32 + mt * 16 + gid;
            size_t ro = (rowbase + r) * 256 + col;
            float2 b = *(const float2*)(b_ge + col);
            float2 o0, o1;
            o0.x = fmaxf(acc[mt][nt][0] + b.x, 0.f);
            o0.y = fmaxf(acc[mt][nt][1] + b.y, 0.f);
            o1.x = fmaxf(acc[mt][nt][2] + b.x, 0.f);
            o1.y = fmaxf(acc[mt][nt][3] + b.y, 0.f);
            *(float2*)(g0 + ro) = o0;
            *(float2*)(g0 + ro + 8 * 256) = o1;
        }
    }
}

// ===========================================================================
// Head: h = relu([g8||l1] @ W1 + b1); out = h @ W2 + b2  (N=1000, 4 tiles)
// ===========================================================================
__global__ __launch_bounds__(NTHREADS, 1) void head_hmma(
    const float* __restrict__ g8, const float* __restrict__ l1,
    const float* __restrict__ b1, const float* __restrict__ b2,
    float* __restrict__ out) {
    extern __shared__ char sm[];
    char* sA_p = sm;
    uint32_t sA = smem_to_u32(sm);
    uint32_t sB = sA + SA_BYTES;
    const int tid = threadIdx.x;
    const size_t rowbase = (size_t)blockIdx.x * 128;
    FRAG_SETUP();

    float acc[2][8][4];
    fill_A_frag(sA_p, g8 + rowbase * 256, 256, tid);
    hmma_gemm_k256(sA, sB, WT_1, acc, tid, true);
    fill_A_frag(sA_p, l1 + rowbase * 256, 256, tid);
    hmma_gemm_k256(sA, sB, WT_1 + BLK_STRIDE, acc, tid, false);

    // h = relu(acc + b1) -> A fragment planes
#pragma unroll
    for (int mt = 0; mt < 2; mt++) {
#pragma unroll
        for (int ntp = 0; ntp < 4; ntp++) {
            int ce = wn * 64 + ntp * 16 + qid * 2;
            float2 bE = *(const float2*)(b1 + ce);
            float2 bO = *(const float2*)(b1 + ce + 8);
            const float* aE = acc[mt][2 * ntp];
            const float* aO = acc[mt][2 * ntp + 1];
            write_A_frag(sA_p, wm * 2 + mt, wn * 4 + ntp, lane,
                         fmaxf(aE[0] + bE.x, 0.f), fmaxf(aE[1] + bE.y, 0.f),
                         fmaxf(aE[2] + bE.x, 0.f), fmaxf(aE[3] + bE.y, 0.f),
                         fmaxf(aO[0] + bO.x, 0.f), fmaxf(aO[1] + bO.y, 0.f),
                         fmaxf(aO[2] + bO.x, 0.f), fmaxf(aO[3] + bO.y, 0.f));
        }
    }

    for (int t = 0; t < 4; t++) {
        hmma_gemm_k256(sA, sB, WT_2 + (size_t)t * BLK_STRIDE, acc, tid, true);
#pragma unroll
        for (int mt = 0; mt < 2; mt++) {
#pragma unroll
            for (int nt = 0; nt < 8; nt++) {
                int col = t * 256 + wn * 64 + nt * 8 + qid * 2;
                if (col < 1000) {
                    int r = wm * 32 + mt * 16 + gid;
                    size_t ro = (rowbase + r) * 1000 + col;
                    float2 b = *(const float2*)(b2 + col);
                    float2 o0, o1;
                    o0.x = acc[mt][nt][0] + b.x;
                    o0.y = acc[mt][nt][1] + b.y;
                    o1.x = acc[mt][nt][2] + b.x;
                    o1.y = acc[mt][nt][3] + b.y;
                    *(float2*)(out + ro) = o0;
                    *(float2*)(out + ro + 8 * 1000) = o1;
                }
            }
        }
    }
}

// ===========================================================================
extern "C" void kernel_launch(void* const* d_in, const int* in_sizes, int n_in,
                              void* d_out, int out_size) {
    (void)in_sizes; (void)n_in; (void)out_size;
    const float* x     = (const float*)d_in[0];
    const float* W_ge  = (const float*)d_in[1];
    const float* b_ge  = (const float*)d_in[2];
    const float* W_eq  = (const float*)d_in[3];
    const float* b_eq  = (const float*)d_in[4];
    const float* W_tr  = (const float*)d_in[5];
    const float* b_tr  = (const float*)d_in[6];
    const float* W_ab  = (const float*)d_in[7];
    const float* b_ab  = (const float*)d_in[8];
    const float* alpha = (const float*)d_in[9];
    const float* W1    = (const float*)d_in[10];
    const float* b1    = (const float*)d_in[11];
    const float* W2    = (const float*)d_in[12];
    const float* b2    = (const float*)d_in[13];
    float* out = (float*)d_out;

    float *gb = nullptr, *lb = nullptr;
    cudaGetSymbolAddress((void**)&gb, g_bufs);
    cudaGetSymbolAddress((void**)&lb, l_bufs);
    auto G = [&](int i) { return gb + (size_t)i * BATCH * DG; };
    auto L = [&](int i) { return lb + (size_t)i * BATCH * DG; };

    cudaFuncSetAttribute(plate_hmma<true>,  cudaFuncAttributeMaxDynamicSharedMemorySize, SMEM_TOTAL);
    cudaFuncSetAttribute(plate_hmma<false>, cudaFuncAttributeMaxDynamicSharedMemorySize, SMEM_TOTAL);
    cudaFuncSetAttribute(encoder_hmma,      cudaFuncAttributeMaxDynamicSharedMemorySize, SMEM_TOTAL);
    cudaFuncSetAttribute(head_hmma,         cudaFuncAttributeMaxDynamicSharedMemorySize, SMEM_TOTAL);

    cudaMemsetAsync(L(9), 0, (size_t)BATCH * DG * sizeof(float));
    prep_kernel<<<512, 256>>>(W_ge, W_eq, W_tr, W_ab, W1, W2);

    dim3 grid(BATCH / 128);

    encoder_hmma<<<grid, NTHREADS, SMEM_TOTAL>>>(x, b_ge, G(0));

    // Sweep 1: descending (g[1..8] None -> g_in = g0)
    for (int n = 8; n >= 1; --n)
        plate_hmma<true><<<grid, NTHREADS, SMEM_TOTAL>>>(G(0), L(n + 1), L(n),
                                                         b_eq, b_tr, b_ab, alpha);
    // Sweep 1: ascending
    for (int n = 1; n <= 8; ++n)
        plate_hmma<false><<<grid, NTHREADS, SMEM_TOTAL>>>(G(n - 1), L(n), G(n),
                                                          b_eq, b_tr, b_ab, alpha);
    // Sweep 2: descending
    for (int n = 8; n >= 1; --n)
        plate_hmma<true><<<grid, NTHREADS, SMEM_TOTAL>>>(G(n - 1), L(n + 1), L(n),
                                                         b_eq, b_tr, b_ab, alpha);
    // Sweep 2: ascending
    for (int n = 1; n <= 8; ++n)
        plate_hmma<false><<<grid, NTHREADS, SMEM_TOTAL>>>(G(n - 1), L(n), G(n),
                                                          b_eq, b_tr, b_ab, alpha);

    head_hmma<<<grid, NTHREADS, SMEM_TOTAL>>>(G(8), L(1), b1, b2, out);
}

// round 10
// speedup vs baseline: 1.0168x; 1.0168x over previous
#include <cuda_runtime.h>
#include <cuda_bf16.h>
#include <cstdint>
#include <cstddef>

#define BATCH 16384
#define DG    256

// CTA tile: 64 rows. SMEM: A fragment planes (hi at 0, lo at +APLANE),
// chunk(mb 0..3, kb 0..15, lane 0..31) = 16B m16k16 A fragment.
#define APLANE    32768
#define SA_BYTES  (2 * APLANE)                     // 65,536
#define SB_PLANE  8192                             // one K16 chunk, one plane (bytes)
#define SB_BUF    (2 * SB_PLANE)                   // hi+lo per chunk = 16,384
#define NSTAGE    3
#define SB_BYTES  (NSTAGE * SB_BUF)                // 49,152 (3-stage ring)
#define SMEM_TOTAL (SA_BYTES + SB_BYTES)           // 114,688 -> 2 CTAs/SM

#define NTHREADS  256
#define MTILE     64

// Packed 256x256 weight block: hi plane [kb16][p16][lane32][8 bf16], lo at +65536.
#define BLK_STRIDE 131072                          // bf16 elems per packed block

// ===========================================================================
// Global scratch (__device__ globals: allocation-free rule)
// ===========================================================================
__device__ float g_bufs[9][BATCH * DG];
__device__ float l_bufs[10][BATCH * DG];
__device__ __align__(128) __nv_bfloat16 WT_eq[BLK_STRIDE];
__device__ __align__(128) __nv_bfloat16 WT_tr[BLK_STRIDE];
__device__ __align__(128) __nv_bfloat16 WT_ab[BLK_STRIDE];
__device__ __align__(128) __nv_bfloat16 WT_ge[2 * BLK_STRIDE];   // K=512: 2 K-half blocks
__device__ __align__(128) __nv_bfloat16 WT_1 [2 * BLK_STRIDE];   // K=512: 2 K-half blocks
__device__ __align__(128) __nv_bfloat16 WT_2 [4 * BLK_STRIDE];   // N=1024: 4 N-tile blocks

__device__ __forceinline__ float sigm(float x) { return 1.0f / (1.0f + expf(-x)); }

__device__ __forceinline__ uint32_t smem_to_u32(const void* p) {
    uint32_t a;
    asm("{ .reg .u64 t; cvta.to.shared.u64 t, %1; cvt.u32.u64 %0, t; }" : "=r"(a) : "l"(p));
    return a;
}

#define CP_ASYNC16(dst_u32, src_ptr) \
    asm volatile("cp.async.cg.shared.global [%0], [%1], 16;" :: "r"(dst_u32), "l"(src_ptr))
#define CP_COMMIT() asm volatile("cp.async.commit_group;" ::: "memory")
#define CP_WAIT1()  asm volatile("cp.async.wait_group 1;" ::: "memory")
#define CP_WAIT0()  asm volatile("cp.async.wait_group 0;" ::: "memory")

#define LDS128(r0, r1, r2, r3, addr) \
    asm volatile("ld.shared.v4.b32 {%0,%1,%2,%3}, [%4];" \
        : "=r"(r0), "=r"(r1), "=r"(r2), "=r"(r3) : "r"(addr))

#define MMA16816(d, a0, a1, a2, a3, b0, b1) \
    asm volatile("mma.sync.aligned.m16n8k16.row.col.f32.bf16.bf16.f32 " \
        "{%0,%1,%2,%3}, {%4,%5,%6,%7}, {%8,%9}, {%0,%1,%2,%3};" \
        : "+f"((d)[0]), "+f"((d)[1]), "+f"((d)[2]), "+f"((d)[3]) \
        : "r"(a0), "r"(a1), "r"(a2), "r"(a3), "r"(b0), "r"(b1))

__device__ __forceinline__ void split2(float2 x, uint32_t& h, uint32_t& l) {
    __nv_bfloat162 hp = __float22bfloat162_rn(x);
    float2 hf = __bfloat1622float2(hp);
    float2 r = make_float2(x.x - hf.x, x.y - hf.y);
    __nv_bfloat162 lp = __float22bfloat162_rn(r);
    h = *reinterpret_cast<uint32_t*>(&hp);
    l = *reinterpret_cast<uint32_t*>(&lp);
}

// Write one A fragment chunk (16B hi + 16B lo) from 8 fp32 values.
__device__ __forceinline__ void write_A_frag(char* sA, int mb, int kb, int lane,
                                             float e0, float e1, float e2, float e3,
                                             float o0, float o1, float o2, float o3) {
    uint32_t h0, l0, h1, l1, h2, l2, h3, l3;
    split2(make_float2(e0, e1), h0, l0);
    split2(make_float2(e2, e3), h1, l1);
    split2(make_float2(o0, o1), h2, l2);
    split2(make_float2(o2, o3), h3, l3);
    uint32_t off = (uint32_t)((mb * 16 + kb) * 32 + lane) * 16;
    *(uint4*)(sA + off) = make_uint4(h0, h1, h2, h3);
    *(uint4*)(sA + APLANE + off) = make_uint4(l0, l1, l2, l3);
}

// ===========================================================================
// prep: pack weights into fragment-order blocks.
// ===========================================================================
__device__ __forceinline__ void pack_store(__nv_bfloat16* dst, int k, int n, float w) {
    int kb = k >> 4;
    int p = n >> 4;
    int lane = (n & 7) * 4 + ((k >> 1) & 3);
    int idx = ((n >> 3) & 1) * 4 + ((k >> 3) & 1) * 2 + (k & 1);
    size_t off = ((size_t)((kb * 16 + p) * 32 + lane)) * 8 + idx;
    __nv_bfloat16 h = __float2bfloat16(w);
    dst[off] = h;
    dst[65536 + off] = __float2bfloat16(w - __bfloat162float(h));
}

__global__ void prep_kernel(const float* __restrict__ Wge, const float* __restrict__ Weq,
                            const float* __restrict__ Wtr, const float* __restrict__ Wab,
                            const float* __restrict__ W1,  const float* __restrict__ W2) {
    int i0 = blockIdx.x * 256 + threadIdx.x;
    int stride = gridDim.x * 256;
    for (int i = i0; i < 11 * 65536; i += stride) {
        int blk = i >> 16, e = i & 65535;
        int k = e >> 8, n = e & 255;
        float w;
        __nv_bfloat16* dst;
        if (blk == 0)      { w = Weq[k * 256 + n]; dst = WT_eq; }
        else if (blk == 1) { w = Wtr[k * 256 + n]; dst = WT_tr; }
        else if (blk == 2) { w = Wab[k * 256 + n]; dst = WT_ab; }
        else if (blk <= 4) { int h = blk - 3; w = Wge[(k + h * 256) * 256 + n]; dst = WT_ge + (size_t)h * BLK_STRIDE; }
        else if (blk <= 6) { int h = blk - 5; w = W1 [(k + h * 256) * 256 + n]; dst = WT_1  + (size_t)h * BLK_STRIDE; }
        else               { int t = blk - 7; int ng = t * 256 + n;
                             w = (ng < 1000) ? W2[k * 1000 + ng] : 0.0f;
                             dst = WT_2 + (size_t)t * BLK_STRIDE; }
        pack_store(dst, k, n, w);
    }
}

// ===========================================================================
// B chunk streaming (K=16 per chunk) via cp.async. 256 threads.
// Chunk kc (0..15): hi 8KB at blk + kc*4096 elems, lo at +65536.
// ===========================================================================
__device__ __forceinline__ void issue_chunk(uint32_t sB, int buf,
                                            const __nv_bfloat16* __restrict__ blk,
                                            int kc, int tid) {
    uint32_t dst = sB + (uint32_t)buf * SB_BUF;
    const __nv_bfloat16* hi = blk + kc * 4096;
    const __nv_bfloat16* lo = blk + 65536 + kc * 4096;
#pragma unroll
    for (int j = 0; j < 2; j++) {
        int e = j * NTHREADS + tid;
        CP_ASYNC16(dst + e * 16, hi + e * 8);
    }
#pragma unroll
    for (int j = 0; j < 2; j++) {
        int e = j * NTHREADS + tid;
        CP_ASYNC16(dst + SB_PLANE + e * 16, lo + e * 8);
    }
}

// ===========================================================================
// HMMA GEMM core: acc[2][8][4] += A(frag planes) @ block^T (bf16x3 split)
// 8 warps: wm (0..1) x wn (0..3); warp tile m32 x n64. CTA tile m64 x n256.
// 3-stage K16 cp.async ring, 2-ahead prefetch, one __syncthreads per chunk.
// Safety invariant: buffer written at kc (nbuf = (kc+2) mod 3) was last READ
// at kc-1 ((kc-1) mod 3 == (kc+2) mod 3), separated by this kc's barrier.
// Ends with __syncthreads.
// ===========================================================================
__device__ __forceinline__ void hmma_gemm_k256(uint32_t sA, uint32_t sB,
                                               const __nv_bfloat16* __restrict__ blk,
                                               float acc[2][8][4],
                                               int tid, bool zero_acc) {
    if (zero_acc) {
#pragma unroll
        for (int mt = 0; mt < 2; mt++)
#pragma unroll
            for (int nt = 0; nt < 8; nt++)
#pragma unroll
                for (int i = 0; i < 4; i++) acc[mt][nt][i] = 0.f;
    }
    const int lane = tid & 31;
    const int wm = (tid >> 5) & 1, wn = tid >> 6;
    // A fragment base for this warp (mb = wm*2 + mt; 8192B per mb block)
    const uint32_t abase = sA + (uint32_t)(wm * 2 * 8192 + lane * 16);

    issue_chunk(sB, 0, blk, 0, tid);
    CP_COMMIT();
    issue_chunk(sB, 1, blk, 1, tid);
    CP_COMMIT();

    int buf = 0;        // buffer holding chunk kc
    int nbuf = 2;       // buffer to fill with chunk kc+2
    for (int kc = 0; kc < 16; kc++) {
        if (kc == 15) { CP_WAIT0(); } else { CP_WAIT1(); }
        __syncthreads();
        if (kc + 2 < 16) {
            issue_chunk(sB, nbuf, blk, kc + 2, tid);
            CP_COMMIT();
        }
        uint32_t sbuf = sB + (uint32_t)buf * SB_BUF;
        buf = (buf == NSTAGE - 1) ? 0 : buf + 1;
        nbuf = (nbuf == NSTAGE - 1) ? 0 : nbuf + 1;

        uint32_t ah[2][4], al[2][4];
#pragma unroll
        for (int mt = 0; mt < 2; mt++) {
            uint32_t aaddr = abase + (uint32_t)(mt * 8192 + kc * 512);
            LDS128(ah[mt][0], ah[mt][1], ah[mt][2], ah[mt][3], aaddr);
            LDS128(al[mt][0], al[mt][1], al[mt][2], al[mt][3], aaddr + APLANE);
        }
#pragma unroll
        for (int ntp = 0; ntp < 4; ntp++) {
            uint32_t ba = sbuf + (uint32_t)((wn * 4 + ntp) * 512 + lane * 16);
            uint32_t h0, h1, h2, h3, l0, l1, l2, l3;
            LDS128(h0, h1, h2, h3, ba);
            LDS128(l0, l1, l2, l3, ba + SB_PLANE);
            float* aE0 = acc[0][2 * ntp];
            float* aO0 = acc[0][2 * ntp + 1];
            float* aE1 = acc[1][2 * ntp];
            float* aO1 = acc[1][2 * ntp + 1];
            // product hh
            MMA16816(aE0, ah[0][0], ah[0][1], ah[0][2], ah[0][3], h0, h1);
            MMA16816(aO0, ah[0][0], ah[0][1], ah[0][2], ah[0][3], h2, h3);
            MMA16816(aE1, ah[1][0], ah[1][1], ah[1][2], ah[1][3], h0, h1);
            MMA16816(aO1, ah[1][0], ah[1][1], ah[1][2], ah[1][3], h2, h3);
            // product hl
            MMA16816(aE0, ah[0][0], ah[0][1], ah[0][2], ah[0][3], l0, l1);
            MMA16816(aO0, ah[0][0], ah[0][1], ah[0][2], ah[0][3], l2, l3);
            MMA16816(aE1, ah[1][0], ah[1][1], ah[1][2], ah[1][3], l0, l1);
            MMA16816(aO1, ah[1][0], ah[1][1], ah[1][2], ah[1][3], l2, l3);
            // product lh
            MMA16816(aE0, al[0][0], al[0][1], al[0][2], al[0][3], h0, h1);
            MMA16816(aO0, al[0][0], al[0][1], al[0][2], al[0][3], h2, h3);
            MMA16816(aE1, al[1][0], al[1][1], al[1][2], al[1][3], h0, h1);
            MMA16816(aO1, al[1][0], al[1][1], al[1][2], al[1][3], h2, h3);
        }
    }
    __syncthreads();
}

// Fill A fragment planes (64 x 256) from row-major gmem. 256 threads.
__device__ __forceinline__ void fill_A_frag(char* sA, const float* __restrict__ src,
                                            int ld, int tid) {
#pragma unroll
    for (int i = 0; i < 8; i++) {
        int idx = i * NTHREADS + tid;           // 0..2047 = (mb*16+kb)*32+lane
        int mb = idx >> 9, kb = (idx >> 5) & 15, ln = idx & 31;
        int gid = ln >> 2, qid = ln & 3;
        const float* p0 = src + (size_t)(mb * 16 + gid) * ld + kb * 16 + 2 * qid;
        float2 x0 = *(const float2*)(p0);                 // row gid,   k low
        float2 x1 = *(const float2*)(p0 + 8 * (size_t)ld);// row gid+8, k low
        float2 x2 = *(const float2*)(p0 + 8);             // row gid,   k high
        float2 x3 = *(const float2*)(p0 + 8 * (size_t)ld + 8);
        write_A_frag(sA, mb, kb, ln, x0.x, x0.y, x1.x, x1.y, x2.x, x2.y, x3.x, x3.y);
    }
}

// Per-fragment index helper (8 warps: wm 0..1, wn 0..3)
#define FRAG_SETUP() \
    const int lane = tid & 31; \
    const int wm = (tid >> 5) & 1, wn = tid >> 6; \
    const int gid = lane >> 2, qid = lane & 3;

// ===========================================================================
// Fused plate kernel (HMMA): 64 rows per CTA, 256 threads, 2 CTAs/SM.
// ===========================================================================
template <bool DESC>
__global__ __launch_bounds__(NTHREADS, 2) void plate_hmma(
    const float* __restrict__ g_in, const float* __restrict__ l_in,
    float* __restrict__ out,
    const float* __restrict__ b_eq, const float* __restrict__ b_tr,
    const float* __restrict__ b_ab, const float* __restrict__ alpha_p) {
    extern __shared__ char sm[];
    char* sA_p = sm;
    uint32_t sA = smem_to_u32(sm);
    uint32_t sB = sA + SA_BYTES;
    const int tid = threadIdx.x;
    const size_t rowbase = (size_t)blockIdx.x * MTILE;
    FRAG_SETUP();

    fill_A_frag(sA_p, l_in + rowbase * 256, 256, tid);

    float acc[2][8][4];
    // GEMM 1: l @ W_eq
    hmma_gemm_k256(sA, sB, WT_eq, acc, tid, true);

    // Epilogue 1: df = g - sigmoid(acc + b_eq) -> A fragment planes
#pragma unroll
    for (int mt = 0; mt < 2; mt++) {
#pragma unroll
        for (int ntp = 0; ntp < 4; ntp++) {
            int ce = wn * 64 + ntp * 16 + qid * 2;
            int r = wm * 32 + mt * 16 + gid;
            size_t ro = (rowbase + r) * 256;
            float2 beE = *(const float2*)(b_eq + ce);
            float2 beO = *(const float2*)(b_eq + ce + 8);
            float2 gE0 = *(const float2*)(g_in + ro + ce);
            float2 gE1 = *(const float2*)(g_in + ro + 8 * 256 + ce);
            float2 gO0 = *(const float2*)(g_in + ro + ce + 8);
            float2 gO1 = *(const float2*)(g_in + ro + 8 * 256 + ce + 8);
            const float* aE = acc[mt][2 * ntp];
            const float* aO = acc[mt][2 * ntp + 1];
            write_A_frag(sA_p, wm * 2 + mt, wn * 4 + ntp, lane,
                         gE0.x - sigm(aE[0] + beE.x), gE0.y - sigm(aE[1] + beE.y),
                         gE1.x - sigm(aE[2] + beE.x), gE1.y - sigm(aE[3] + beE.y),
                         gO0.x - sigm(aO[0] + beO.x), gO0.y - sigm(aO[1] + beO.y),
                         gO1.x - sigm(aO[2] + beO.x), gO1.y - sigm(aO[3] + beO.y));
        }
    }

    // GEMM 2: df @ W_tr
    hmma_gemm_k256(sA, sB, WT_tr, acc, tid, true);

    const float alpha = *alpha_p;

    if (!DESC) {
        // out = g - alpha*(acc + b_tr)
#pragma unroll
        for (int mt = 0; mt < 2; mt++) {
#pragma unroll
            for (int nt = 0; nt < 8; nt++) {
                int col = wn * 64 + nt * 8 + qid * 2;
                int r = wm * 32 + mt * 16 + gid;
                size_t ro = (rowbase + r) * 256 + col;
                float2 bt = *(const float2*)(b_tr + col);
                float2 g0 = *(const float2*)(g_in + ro);
                float2 g1 = *(const float2*)(g_in + ro + 8 * 256);
                float2 o0, o1;
                o0.x = g0.x - alpha * (acc[mt][nt][0] + bt.x);
                o0.y = g0.y - alpha * (acc[mt][nt][1] + bt.y);
                o1.x = g1.x - alpha * (acc[mt][nt][2] + bt.x);
                o1.y = g1.y - alpha * (acc[mt][nt][3] + bt.y);
                *(float2*)(out + ro) = o0;
                *(float2*)(out + ro + 8 * 256) = o1;
            }
        }
    } else {
        // delta = alpha*(acc + b_tr) -> A fragment planes
#pragma unroll
        for (int mt = 0; mt < 2; mt++) {
#pragma unroll
            for (int ntp = 0; ntp < 4; ntp++) {
                int ce = wn * 64 + ntp * 16 + qid * 2;
                float2 btE = *(const float2*)(b_tr + ce);
                float2 btO = *(const float2*)(b_tr + ce + 8);
                const float* aE = acc[mt][2 * ntp];
                const float* aO = acc[mt][2 * ntp + 1];
                write_A_frag(sA_p, wm * 2 + mt, wn * 4 + ntp, lane,
                             alpha * (aE[0] + btE.x), alpha * (aE[1] + btE.y),
                             alpha * (aE[2] + btE.x), alpha * (aE[3] + btE.y),
                             alpha * (aO[0] + btO.x), alpha * (aO[1] + btO.y),
                             alpha * (aO[2] + btO.x), alpha * (aO[3] + btO.y));
            }
        }

        // GEMM 3: delta @ W_ab
        hmma_gemm_k256(sA, sB, WT_ab, acc, tid, true);

        // out = l + acc + b_ab
#pragma unroll
        for (int mt = 0; mt < 2; mt++) {
#pragma unroll
            for (int nt = 0; nt < 8; nt++) {
                int col = wn * 64 + nt * 8 + qid * 2;
                int r = wm * 32 + mt * 16 + gid;
                size_t ro = (rowbase + r) * 256 + col;
                float2 ba = *(const float2*)(b_ab + col);
                float2 l0 = *(const float2*)(l_in + ro);
                float2 l1 = *(const float2*)(l_in + ro + 8 * 256);
                float2 o0, o1;
                o0.x = l0.x + acc[mt][nt][0] + ba.x;
                o0.y = l0.y + acc[mt][nt][1] + ba.y;
                o1.x = l1.x + acc[mt][nt][2] + ba.x;
                o1.y = l1.y + acc[mt][nt][3] + ba.y;
                *(float2*)(out + ro) = o0;
                *(float2*)(out + ro + 8 * 256) = o1;
            }
        }
    }
}

// ===========================================================================
// Encoder: g0 = relu(x @ W_ge + b_ge), K = 512 as two accumulated K=256 passes
// ===========================================================================
__global__ __launch_bounds__(NTHREADS, 2) void encoder_hmma(
    const float* __restrict__ x, const float* __restrict__ b_ge,
    float* __restrict__ g0) {
    extern __shared__ char sm[];
    char* sA_p = sm;
    uint32_t sA = smem_to_u32(sm);
    uint32_t sB = sA + SA_BYTES;
    const int tid = threadIdx.x;
    const size_t rowbase = (size_t)blockIdx.x * MTILE;
    FRAG_SETUP();

    float acc[2][8][4];
    fill_A_frag(sA_p, x + rowbase * 512, 512, tid);
    hmma_gemm_k256(sA, sB, WT_ge, acc, tid, true);
    fill_A_frag(sA_p, x + rowbase * 512 + 256, 512, tid);
    hmma_gemm_k256(sA, sB, WT_ge + BLK_STRIDE, acc, tid, false);

#pragma unroll
    for (int mt = 0; mt < 2; mt++) {
#pragma unroll
        for (int nt = 0; nt < 8; nt++) {
            int col = wn * 64 + nt * 8 + qid * 2;
            int r = wm * 32 + mt * 16 + gid;
            size_t ro = (rowbase + r) * 256 + col;
            float2 b = *(const float2*)(b_ge + col);
            float2 o0, o1;
            o0.x = fmaxf(acc[mt][nt][0] + b.x, 0.f);
            o0.y = fmaxf(acc[mt][nt][1] + b.y, 0.f);
            o1.x = fmaxf(acc[mt][nt][2] + b.x, 0.f);
            o1.y = fmaxf(acc[mt][nt][3] + b.y, 0.f);
            *(float2*)(g0 + ro) = o0;
            *(float2*)(g0 + ro + 8 * 256) = o1;
        }
    }
}

// ===========================================================================
// Head: h = relu([g8||l1] @ W1 + b1); out = h @ W2 + b2  (N=1000, 4 tiles)
// ===========================================================================
__global__ __launch_bounds__(NTHREADS, 2) void head_hmma(
    const float* __restrict__ g8, const float* __restrict__ l1,
    const float* __restrict__ b1, const float* __restrict__ b2,
    float* __restrict__ out) {
    extern __shared__ char sm[];
    char* sA_p = sm;
    uint32_t sA = smem_to_u32(sm);
    uint32_t sB = sA + SA_BYTES;
    const int tid = threadIdx.x;
    const size_t rowbase = (size_t)blockIdx.x * MTILE;
    FRAG_SETUP();

    float acc[2][8][4];
    fill_A_frag(sA_p, g8 + rowbase * 256, 256, tid);
    hmma_gemm_k256(sA, sB, WT_1, acc, tid, true);
    fill_A_frag(sA_p, l1 + rowbase * 256, 256, tid);
    hmma_gemm_k256(sA, sB, WT_1 + BLK_STRIDE, acc, tid, false);

    // h = relu(acc + b1) -> A fragment planes
#pragma unroll
    for (int mt = 0; mt < 2; mt++) {
#pragma unroll
        for (int ntp = 0; ntp < 4; ntp++) {
            int ce = wn * 64 + ntp * 16 + qid * 2;
            float2 bE = *(const float2*)(b1 + ce);
            float2 bO = *(const float2*)(b1 + ce + 8);
            const float* aE = acc[mt][2 * ntp];
            const float* aO = acc[mt][2 * ntp + 1];
            write_A_frag(sA_p, wm * 2 + mt, wn * 4 + ntp, lane,
                         fmaxf(aE[0] + bE.x, 0.f), fmaxf(aE[1] + bE.y, 0.f),
                         fmaxf(aE[2] + bE.x, 0.f), fmaxf(aE[3] + bE.y, 0.f),
                         fmaxf(aO[0] + bO.x, 0.f), fmaxf(aO[1] + bO.y, 0.f),
                         fmaxf(aO[2] + bO.x, 0.f), fmaxf(aO[3] + bO.y, 0.f));
        }
    }

    for (int t = 0; t < 4; t++) {
        hmma_gemm_k256(sA, sB, WT_2 + (size_t)t * BLK_STRIDE, acc, tid, true);
#pragma unroll
        for (int mt = 0; mt < 2; mt++) {
#pragma unroll
            for (int nt = 0; nt < 8; nt++) {
                int col = t * 256 + wn * 64 + nt * 8 + qid * 2;
                if (col < 1000) {
                    int r = wm * 32 + mt * 16 + gid;
                    size_t ro = (rowbase + r) * 1000 + col;
                    float2 b = *(const float2*)(b2 + col);
                    float2 o0, o1;
                    o0.x = acc[mt][nt][0] + b.x;
                    o0.y = acc[mt][nt][1] + b.y;
                    o1.x = acc[mt][nt][2] + b.x;
                    o1.y = acc[mt][nt][3] + b.y;
                    *(float2*)(out + ro) = o0;
                    *(float2*)(out + ro + 8 * 1000) = o1;
                }
            }
        }
    }
}

// ===========================================================================
extern "C" void kernel_launch(void* const* d_in, const int* in_sizes, int n_in,
                              void* d_out, int out_size) {
    (void)in_sizes; (void)n_in; (void)out_size;
    const float* x     = (const float*)d_in[0];
    const float* W_ge  = (const float*)d_in[1];
    const float* b_ge  = (const float*)d_in[2];
    const float* W_eq  = (const float*)d_in[3];
    const float* b_eq  = (const float*)d_in[4];
    const float* W_tr  = (const float*)d_in[5];
    const float* b_tr  = (const float*)d_in[6];
    const float* W_ab  = (const float*)d_in[7];
    const float* b_ab  = (const float*)d_in[8];
    const float* alpha = (const float*)d_in[9];
    const float* W1    = (const float*)d_in[10];
    const float* b1    = (const float*)d_in[11];
    const float* W2    = (const float*)d_in[12];
    const float* b2    = (const float*)d_in[13];
    float* out = (float*)d_out;

    float *gb = nullptr, *lb = nullptr;
    cudaGetSymbolAddress((void**)&gb, g_bufs);
    cudaGetSymbolAddress((void**)&lb, l_bufs);
    auto G = [&](int i) { return gb + (size_t)i * BATCH * DG; };
    auto L = [&](int i) { return lb + (size_t)i * BATCH * DG; };

    cudaFuncSetAttribute(plate_hmma<true>,  cudaFuncAttributeMaxDynamicSharedMemorySize, SMEM_TOTAL);
    cudaFuncSetAttribute(plate_hmma<false>, cudaFuncAttributeMaxDynamicSharedMemorySize, SMEM_TOTAL);
    cudaFuncSetAttribute(encoder_hmma,      cudaFuncAttributeMaxDynamicSharedMemorySize, SMEM_TOTAL);
    cudaFuncSetAttribute(head_hmma,         cudaFuncAttributeMaxDynamicSharedMemorySize, SMEM_TOTAL);

    cudaMemsetAsync(L(9), 0, (size_t)BATCH * DG * sizeof(float));
    prep_kernel<<<512, 256>>>(W_ge, W_eq, W_tr, W_ab, W1, W2);

    dim3 grid(BATCH / MTILE);   // 256 CTAs = one full wave at 2 CTAs/SM

    encoder_hmma<<<grid, NTHREADS, SMEM_TOTAL>>>(x, b_ge, G(0));

    // Sweep 1: descending (g[1..8] None -> g_in = g0)
    for (int n = 8; n >= 1; --n)
        plate_hmma<true><<<grid, NTHREADS, SMEM_TOTAL>>>(G(0), L(n + 1), L(n),
                                                         b_eq, b_tr, b_ab, alpha);
    // Sweep 1: ascending
    for (int n = 1; n <= 8; ++n)
        plate_hmma<false><<<grid, NTHREADS, SMEM_TOTAL>>>(G(n - 1), L(n), G(n),
                                                          b_eq, b_tr, b_ab, alpha);
    // Sweep 2: descending
    for (int n = 8; n >= 1; --n)
        plate_hmma<true><<<grid, NTHREADS, SMEM_TOTAL>>>(G(n - 1), L(n + 1), L(n),
                                                         b_eq, b_tr, b_ab, alpha);
    // Sweep 2: ascending
    for (int n = 1; n <= 8; ++n)
        plate_hmma<false><<<grid, NTHREADS, SMEM_TOTAL>>>(G(n - 1), L(n), G(n),
                                                          b_eq, b_tr, b_ab, alpha);

    head_hmma<<<grid, NTHREADS, SMEM_TOTAL>>>(G(8), L(1), b1, b2, out);
}

// round 11
// speedup vs baseline: 1.1778x; 1.1584x over previous
#include <cuda_runtime.h>
#include <cuda_bf16.h>
#include <cstdint>
#include <cstddef>

#define BATCH 16384
#define DG    256

// CTA tile: 64 rows. SMEM: A fragment planes only (hi at 0, lo at +APLANE).
// Chunk(mb 0..3, kb 0..15, lane 0..31) = 16B m16k16 A fragment.
#define APLANE    32768
#define SA_BYTES  (2 * APLANE)                     // 65,536 -> 2 CTAs/SM easily
#define SMEM_TOTAL SA_BYTES

#define NTHREADS  256
#define MTILE     64

// Packed 256x256 weight block: hi plane [kb16][p16][lane32][8 bf16], lo at +65536.
#define BLK_STRIDE 131072                          // bf16 elems per packed block

// ===========================================================================
// Global scratch (__device__ globals: allocation-free rule)
// ===========================================================================
__device__ float g_bufs[9][BATCH * DG];
__device__ float l_bufs[10][BATCH * DG];
__device__ __align__(128) __nv_bfloat16 WT_eq[BLK_STRIDE];
__device__ __align__(128) __nv_bfloat16 WT_tr[BLK_STRIDE];
__device__ __align__(128) __nv_bfloat16 WT_ab[BLK_STRIDE];
__device__ __align__(128) __nv_bfloat16 WT_ge[2 * BLK_STRIDE];   // K=512: 2 K-half blocks
__device__ __align__(128) __nv_bfloat16 WT_1 [2 * BLK_STRIDE];   // K=512: 2 K-half blocks
__device__ __align__(128) __nv_bfloat16 WT_2 [4 * BLK_STRIDE];   // N=1024: 4 N-tile blocks

__device__ __forceinline__ float sigm(float x) { return 1.0f / (1.0f + expf(-x)); }

__device__ __forceinline__ uint32_t smem_to_u32(const void* p) {
    uint32_t a;
    asm("{ .reg .u64 t; cvta.to.shared.u64 t, %1; cvt.u32.u64 %0, t; }" : "=r"(a) : "l"(p));
    return a;
}

#define LDS128(r0, r1, r2, r3, addr) \
    asm volatile("ld.shared.v4.b32 {%0,%1,%2,%3}, [%4];" \
        : "=r"(r0), "=r"(r1), "=r"(r2), "=r"(r3) : "r"(addr))

#define LDG128(r0, r1, r2, r3, ptr) \
    asm volatile("ld.global.nc.v4.u32 {%0,%1,%2,%3}, [%4];" \
        : "=r"(r0), "=r"(r1), "=r"(r2), "=r"(r3) : "l"(ptr))

#define MMA16816(d, a0, a1, a2, a3, b0, b1) \
    asm volatile("mma.sync.aligned.m16n8k16.row.col.f32.bf16.bf16.f32 " \
        "{%0,%1,%2,%3}, {%4,%5,%6,%7}, {%8,%9}, {%0,%1,%2,%3};" \
        : "+f"((d)[0]), "+f"((d)[1]), "+f"((d)[2]), "+f"((d)[3]) \
        : "r"(a0), "r"(a1), "r"(a2), "r"(a3), "r"(b0), "r"(b1))

__device__ __forceinline__ void split2(float2 x, uint32_t& h, uint32_t& l) {
    __nv_bfloat162 hp = __float22bfloat162_rn(x);
    float2 hf = __bfloat1622float2(hp);
    float2 r = make_float2(x.x - hf.x, x.y - hf.y);
    __nv_bfloat162 lp = __float22bfloat162_rn(r);
    h = *reinterpret_cast<uint32_t*>(&hp);
    l = *reinterpret_cast<uint32_t*>(&lp);
}

// Write one A fragment chunk (16B hi + 16B lo) from 8 fp32 values.
__device__ __forceinline__ void write_A_frag(char* sA, int mb, int kb, int lane,
                                             float e0, float e1, float e2, float e3,
                                             float o0, float o1, float o2, float o3) {
    uint32_t h0, l0, h1, l1, h2, l2, h3, l3;
    split2(make_float2(e0, e1), h0, l0);
    split2(make_float2(e2, e3), h1, l1);
    split2(make_float2(o0, o1), h2, l2);
    split2(make_float2(o2, o3), h3, l3);
    uint32_t off = (uint32_t)((mb * 16 + kb) * 32 + lane) * 16;
    *(uint4*)(sA + off) = make_uint4(h0, h1, h2, h3);
    *(uint4*)(sA + APLANE + off) = make_uint4(l0, l1, l2, l3);
}

// ===========================================================================
// prep: pack weights into fragment-order blocks.
// ===========================================================================
__device__ __forceinline__ void pack_store(__nv_bfloat16* dst, int k, int n, float w) {
    int kb = k >> 4;
    int p = n >> 4;
    int lane = (n & 7) * 4 + ((k >> 1) & 3);
    int idx = ((n >> 3) & 1) * 4 + ((k >> 3) & 1) * 2 + (k & 1);
    size_t off = ((size_t)((kb * 16 + p) * 32 + lane)) * 8 + idx;
    __nv_bfloat16 h = __float2bfloat16(w);
    dst[off] = h;
    dst[65536 + off] = __float2bfloat16(w - __bfloat162float(h));
}

__global__ void prep_kernel(const float* __restrict__ Wge, const float* __restrict__ Weq,
                            const float* __restrict__ Wtr, const float* __restrict__ Wab,
                            const float* __restrict__ W1,  const float* __restrict__ W2) {
    int i0 = blockIdx.x * 256 + threadIdx.x;
    int stride = gridDim.x * 256;
    for (int i = i0; i < 11 * 65536; i += stride) {
        int blk = i >> 16, e = i & 65535;
        int k = e >> 8, n = e & 255;
        float w;
        __nv_bfloat16* dst;
        if (blk == 0)      { w = Weq[k * 256 + n]; dst = WT_eq; }
        else if (blk == 1) { w = Wtr[k * 256 + n]; dst = WT_tr; }
        else if (blk == 2) { w = Wab[k * 256 + n]; dst = WT_ab; }
        else if (blk <= 4) { int h = blk - 3; w = Wge[(k + h * 256) * 256 + n]; dst = WT_ge + (size_t)h * BLK_STRIDE; }
        else if (blk <= 6) { int h = blk - 5; w = W1 [(k + h * 256) * 256 + n]; dst = WT_1  + (size_t)h * BLK_STRIDE; }
        else               { int t = blk - 7; int ng = t * 256 + n;
                             w = (ng < 1000) ? W2[k * 1000 + ng] : 0.0f;
                             dst = WT_2 + (size_t)t * BLK_STRIDE; }
        pack_store(dst, k, n, w);
    }
}

// ===========================================================================
// HMMA GEMM core: acc[2][8][4] += A(frag planes) @ block^T (bf16x3 split)
// 8 warps: wm (0..1) x wn (0..3); warp tile m32 x n64. CTA tile m64 x n256.
// B fragments read DIRECTLY from gmem (coalesced 512B LDG.128 per warp) —
// no SMEM B, no cp.async, NO barriers inside the K loop. Warps run free;
// LDG latency covered by the other warps' MMAs (4 warps/SMSP at 2 CTAs/SM).
// One __syncthreads at entry (A-write -> A-read) and exit (A-read -> A-write).
// ===========================================================================
__device__ __forceinline__ void hmma_gemm_k256(uint32_t sA,
                                               const __nv_bfloat16* __restrict__ blk,
                                               float acc[2][8][4],
                                               int tid, bool zero_acc) {
    if (zero_acc) {
#pragma unroll
        for (int mt = 0; mt < 2; mt++)
#pragma unroll
            for (int nt = 0; nt < 8; nt++)
#pragma unroll
                for (int i = 0; i < 4; i++) acc[mt][nt][i] = 0.f;
    }
    const int lane = tid & 31;
    const int wm = (tid >> 5) & 1, wn = tid >> 6;
    const uint32_t abase = sA + (uint32_t)(wm * 2 * 8192 + lane * 16);
    // B fragment base for this warp: p = wn*4 + ntp, elem = ((kc*16+p)*32+lane)*8
    const __nv_bfloat16* bbase = blk + ((size_t)(wn * 4) * 32 + lane) * 8;

    __syncthreads();   // A fragments visible to all warps

#pragma unroll 4
    for (int kc = 0; kc < 16; kc++) {
        const __nv_bfloat16* bk = bbase + (size_t)kc * 16 * 32 * 8;
        // Issue all B loads first (MLP=8)
        uint32_t bh[4][4], bl[4][4];
#pragma unroll
        for (int ntp = 0; ntp < 4; ntp++) {
            const __nv_bfloat16* bp = bk + ntp * 256;
            LDG128(bh[ntp][0], bh[ntp][1], bh[ntp][2], bh[ntp][3], bp);
            LDG128(bl[ntp][0], bl[ntp][1], bl[ntp][2], bl[ntp][3], bp + 65536);
        }
        // A fragments (LDS latency overlaps LDG)
        uint32_t ah[2][4], al[2][4];
#pragma unroll
        for (int mt = 0; mt < 2; mt++) {
            uint32_t aaddr = abase + (uint32_t)(mt * 8192 + kc * 512);
            LDS128(ah[mt][0], ah[mt][1], ah[mt][2], ah[mt][3], aaddr);
            LDS128(al[mt][0], al[mt][1], al[mt][2], al[mt][3], aaddr + APLANE);
        }
#pragma unroll
        for (int ntp = 0; ntp < 4; ntp++) {
            float* aE0 = acc[0][2 * ntp];
            float* aO0 = acc[0][2 * ntp + 1];
            float* aE1 = acc[1][2 * ntp];
            float* aO1 = acc[1][2 * ntp + 1];
            // product hh
            MMA16816(aE0, ah[0][0], ah[0][1], ah[0][2], ah[0][3], bh[ntp][0], bh[ntp][1]);
            MMA16816(aO0, ah[0][0], ah[0][1], ah[0][2], ah[0][3], bh[ntp][2], bh[ntp][3]);
            MMA16816(aE1, ah[1][0], ah[1][1], ah[1][2], ah[1][3], bh[ntp][0], bh[ntp][1]);
            MMA16816(aO1, ah[1][0], ah[1][1], ah[1][2], ah[1][3], bh[ntp][2], bh[ntp][3]);
            // product hl
            MMA16816(aE0, ah[0][0], ah[0][1], ah[0][2], ah[0][3], bl[ntp][0], bl[ntp][1]);
            MMA16816(aO0, ah[0][0], ah[0][1], ah[0][2], ah[0][3], bl[ntp][2], bl[ntp][3]);
            MMA16816(aE1, ah[1][0], ah[1][1], ah[1][2], ah[1][3], bl[ntp][0], bl[ntp][1]);
            MMA16816(aO1, ah[1][0], ah[1][1], ah[1][2], ah[1][3], bl[ntp][2], bl[ntp][3]);
            // product lh
            MMA16816(aE0, al[0][0], al[0][1], al[0][2], al[0][3], bh[ntp][0], bh[ntp][1]);
            MMA16816(aO0, al[0][0], al[0][1], al[0][2], al[0][3], bh[ntp][2], bh[ntp][3]);
            MMA16816(aE1, al[1][0], al[1][1], al[1][2], al[1][3], bh[ntp][0], bh[ntp][1]);
            MMA16816(aO1, al[1][0], al[1][1], al[1][2], al[1][3], bh[ntp][2], bh[ntp][3]);
        }
    }
    __syncthreads();   // all A reads done before caller rewrites A
}

// Fill A fragment planes (64 x 256) from row-major gmem. 256 threads.
__device__ __forceinline__ void fill_A_frag(char* sA, const float* __restrict__ src,
                                            int ld, int tid) {
#pragma unroll
    for (int i = 0; i < 8; i++) {
        int idx = i * NTHREADS + tid;           // 0..2047 = (mb*16+kb)*32+lane
        int mb = idx >> 9, kb = (idx >> 5) & 15, ln = idx & 31;
        int gid = ln >> 2, qid = ln & 3;
        const float* p0 = src + (size_t)(mb * 16 + gid) * ld + kb * 16 + 2 * qid;
        float2 x0 = *(const float2*)(p0);                 // row gid,   k low
        float2 x1 = *(const float2*)(p0 + 8 * (size_t)ld);// row gid+8, k low
        float2 x2 = *(const float2*)(p0 + 8);             // row gid,   k high
        float2 x3 = *(const float2*)(p0 + 8 * (size_t)ld + 8);
        write_A_frag(sA, mb, kb, ln, x0.x, x0.y, x1.x, x1.y, x2.x, x2.y, x3.x, x3.y);
    }
}

// Per-fragment index helper (8 warps: wm 0..1, wn 0..3)
#define FRAG_SETUP() \
    const int lane = tid & 31; \
    const int wm = (tid >> 5) & 1, wn = tid >> 6; \
    const int gid = lane >> 2, qid = lane & 3;

// ===========================================================================
// Fused plate kernel (HMMA): 64 rows per CTA, 256 threads, 2 CTAs/SM.
// ===========================================================================
template <bool DESC>
__global__ __launch_bounds__(NTHREADS, 2) void plate_hmma(
    const float* __restrict__ g_in, const float* __restrict__ l_in,
    float* __restrict__ out,
    const float* __restrict__ b_eq, const float* __restrict__ b_tr,
    const float* __restrict__ b_ab, const float* __restrict__ alpha_p) {
    extern __shared__ char sm[];
    char* sA_p = sm;
    uint32_t sA = smem_to_u32(sm);
    const int tid = threadIdx.x;
    const size_t rowbase = (size_t)blockIdx.x * MTILE;
    FRAG_SETUP();

    fill_A_frag(sA_p, l_in + rowbase * 256, 256, tid);

    float acc[2][8][4];
    // GEMM 1: l @ W_eq
    hmma_gemm_k256(sA, WT_eq, acc, tid, true);

    // Epilogue 1: df = g - sigmoid(acc + b_eq) -> A fragment planes
#pragma unroll
    for (int mt = 0; mt < 2; mt++) {
#pragma unroll
        for (int ntp = 0; ntp < 4; ntp++) {
            int ce = wn * 64 + ntp * 16 + qid * 2;
            int r = wm * 32 + mt * 16 + gid;
            size_t ro = (rowbase + r) * 256;
            float2 beE = *(const float2*)(b_eq + ce);
            float2 beO = *(const float2*)(b_eq + ce + 8);
            float2 gE0 = *(const float2*)(g_in + ro + ce);
            float2 gE1 = *(const float2*)(g_in + ro + 8 * 256 + ce);
            float2 gO0 = *(const float2*)(g_in + ro + ce + 8);
            float2 gO1 = *(const float2*)(g_in + ro + 8 * 256 + ce + 8);
            const float* aE = acc[mt][2 * ntp];
            const float* aO = acc[mt][2 * ntp + 1];
            write_A_frag(sA_p, wm * 2 + mt, wn * 4 + ntp, lane,
                         gE0.x - sigm(aE[0] + beE.x), gE0.y - sigm(aE[1] + beE.y),
                         gE1.x - sigm(aE[2] + beE.x), gE1.y - sigm(aE[3] + beE.y),
                         gO0.x - sigm(aO[0] + beO.x), gO0.y - sigm(aO[1] + beO.y),
                         gO1.x - sigm(aO[2] + beO.x), gO1.y - sigm(aO[3] + beO.y));
        }
    }

    // GEMM 2: df @ W_tr
    hmma_gemm_k256(sA, WT_tr, acc, tid, true);

    const float alpha = *alpha_p;

    if (!DESC) {
        // out = g - alpha*(acc + b_tr)
#pragma unroll
        for (int mt = 0; mt < 2; mt++) {
#pragma unroll
            for (int nt = 0; nt < 8; nt++) {
                int col = wn * 64 + nt * 8 + qid * 2;
                int r = wm * 32 + mt * 16 + gid;
                size_t ro = (rowbase + r) * 256 + col;
                float2 bt = *(const float2*)(b_tr + col);
                float2 g0 = *(const float2*)(g_in + ro);
                float2 g1 = *(const float2*)(g_in + ro + 8 * 256);
                float2 o0, o1;
                o0.x = g0.x - alpha * (acc[mt][nt][0] + bt.x);
                o0.y = g0.y - alpha * (acc[mt][nt][1] + bt.y);
                o1.x = g1.x - alpha * (acc[mt][nt][2] + bt.x);
                o1.y = g1.y - alpha * (acc[mt][nt][3] + bt.y);
                *(float2*)(out + ro) = o0;
                *(float2*)(out + ro + 8 * 256) = o1;
            }
        }
    } else {
        // delta = alpha*(acc + b_tr) -> A fragment planes
#pragma unroll
        for (int mt = 0; mt < 2; mt++) {
#pragma unroll
            for (int ntp = 0; ntp < 4; ntp++) {
                int ce = wn * 64 + ntp * 16 + qid * 2;
                float2 btE = *(const float2*)(b_tr + ce);
                float2 btO = *(const float2*)(b_tr + ce + 8);
                const float* aE = acc[mt][2 * ntp];
                const float* aO = acc[mt][2 * ntp + 1];
                write_A_frag(sA_p, wm * 2 + mt, wn * 4 + ntp, lane,
                             alpha * (aE[0] + btE.x), alpha * (aE[1] + btE.y),
                             alpha * (aE[2] + btE.x), alpha * (aE[3] + btE.y),
                             alpha * (aO[0] + btO.x), alpha * (aO[1] + btO.y),
                             alpha * (aO[2] + btO.x), alpha * (aO[3] + btO.y));
            }
        }

        // GEMM 3: delta @ W_ab
        hmma_gemm_k256(sA, WT_ab, acc, tid, true);

        // out = l + acc + b_ab
#pragma unroll
        for (int mt = 0; mt < 2; mt++) {
#pragma unroll
            for (int nt = 0; nt < 8; nt++) {
                int col = wn * 64 + nt * 8 + qid * 2;
                int r = wm * 32 + mt * 16 + gid;
                size_t ro = (rowbase + r) * 256 + col;
                float2 ba = *(const float2*)(b_ab + col);
                float2 l0 = *(const float2*)(l_in + ro);
                float2 l1 = *(const float2*)(l_in + ro + 8 * 256);
                float2 o0, o1;
                o0.x = l0.x + acc[mt][nt][0] + ba.x;
                o0.y = l0.y + acc[mt][nt][1] + ba.y;
                o1.x = l1.x + acc[mt][nt][2] + ba.x;
                o1.y = l1.y + acc[mt][nt][3] + ba.y;
                *(float2*)(out + ro) = o0;
                *(float2*)(out + ro + 8 * 256) = o1;
            }
        }
    }
}

// ===========================================================================
// Encoder: g0 = relu(x @ W_ge + b_ge), K = 512 as two accumulated K=256 passes
// ===========================================================================
__global__ __launch_bounds__(NTHREADS, 2) void encoder_hmma(
    const float* __restrict__ x, const float* __restrict__ b_ge,
    float* __restrict__ g0) {
    extern __shared__ char sm[];
    char* sA_p = sm;
    uint32_t sA = smem_to_u32(sm);
    const int tid = threadIdx.x;
    const size_t rowbase = (size_t)blockIdx.x * MTILE;
    FRAG_SETUP();

    float acc[2][8][4];
    fill_A_frag(sA_p, x + rowbase * 512, 512, tid);
    hmma_gemm_k256(sA, WT_ge, acc, tid, true);
    fill_A_frag(sA_p, x + rowbase * 512 + 256, 512, tid);
    hmma_gemm_k256(sA, WT_ge + BLK_STRIDE, acc, tid, false);

#pragma unroll
    for (int mt = 0; mt < 2; mt++) {
#pragma unroll
        for (int nt = 0; nt < 8; nt++) {
            int col = wn * 64 + nt * 8 + qid * 2;
            int r = wm * 32 + mt * 16 + gid;
            size_t ro = (rowbase + r) * 256 + col;
            float2 b = *(const float2*)(b_ge + col);
            float2 o0, o1;
            o0.x = fmaxf(acc[mt][nt][0] + b.x, 0.f);
            o0.y = fmaxf(acc[mt][nt][1] + b.y, 0.f);
            o1.x = fmaxf(acc[mt][nt][2] + b.x, 0.f);
            o1.y = fmaxf(acc[mt][nt][3] + b.y, 0.f);
            *(float2*)(g0 + ro) = o0;
            *(float2*)(g0 + ro + 8 * 256) = o1;
        }
    }
}

// ===========================================================================
// Head: h = relu([g8||l1] @ W1 + b1); out = h @ W2 + b2  (N=1000, 4 tiles)
// ===========================================================================
__global__ __launch_bounds__(NTHREADS, 2) void head_hmma(
    const float* __restrict__ g8, const float* __restrict__ l1,
    const float* __restrict__ b1, const float* __restrict__ b2,
    float* __restrict__ out) {
    extern __shared__ char sm[];
    char* sA_p = sm;
    uint32_t sA = smem_to_u32(sm);
    const int tid = threadIdx.x;
    const size_t rowbase = (size_t)blockIdx.x * MTILE;
    FRAG_SETUP();

    float acc[2][8][4];
    fill_A_frag(sA_p, g8 + rowbase * 256, 256, tid);
    hmma_gemm_k256(sA, WT_1, acc, tid, true);
    fill_A_frag(sA_p, l1 + rowbase * 256, 256, tid);
    hmma_gemm_k256(sA, WT_1 + BLK_STRIDE, acc, tid, false);

    // h = relu(acc + b1) -> A fragment planes
#pragma unroll
    for (int mt = 0; mt < 2; mt++) {
#pragma unroll
        for (int ntp = 0; ntp < 4; ntp++) {
            int ce = wn * 64 + ntp * 16 + qid * 2;
            float2 bE = *(const float2*)(b1 + ce);
            float2 bO = *(const float2*)(b1 + ce + 8);
            const float* aE = acc[mt][2 * ntp];
            const float* aO = acc[mt][2 * ntp + 1];
            write_A_frag(sA_p, wm * 2 + mt, wn * 4 + ntp, lane,
                         fmaxf(aE[0] + bE.x, 0.f), fmaxf(aE[1] + bE.y, 0.f),
                         fmaxf(aE[2] + bE.x, 0.f), fmaxf(aE[3] + bE.y, 0.f),
                         fmaxf(aO[0] + bO.x, 0.f), fmaxf(aO[1] + bO.y, 0.f),
                         fmaxf(aO[2] + bO.x, 0.f), fmaxf(aO[3] + bO.y, 0.f));
        }
    }

    for (int t = 0; t < 4; t++) {
        hmma_gemm_k256(sA, WT_2 + (size_t)t * BLK_STRIDE, acc, tid, true);
#pragma unroll
        for (int mt = 0; mt < 2; mt++) {
#pragma unroll
            for (int nt = 0; nt < 8; nt++) {
                int col = t * 256 + wn * 64 + nt * 8 + qid * 2;
                if (col < 1000) {
                    int r = wm * 32 + mt * 16 + gid;
                    size_t ro = (rowbase + r) * 1000 + col;
                    float2 b = *(const float2*)(b2 + col);
                    float2 o0, o1;
                    o0.x = acc[mt][nt][0] + b.x;
                    o0.y = acc[mt][nt][1] + b.y;
                    o1.x = acc[mt][nt][2] + b.x;
                    o1.y = acc[mt][nt][3] + b.y;
                    *(float2*)(out + ro) = o0;
                    *(float2*)(out + ro + 8 * 1000) = o1;
                }
            }
        }
    }
}

// ===========================================================================
extern "C" void kernel_launch(void* const* d_in, const int* in_sizes, int n_in,
                              void* d_out, int out_size) {
    (void)in_sizes; (void)n_in; (void)out_size;
    const float* x     = (const float*)d_in[0];
    const float* W_ge  = (const float*)d_in[1];
    const float* b_ge  = (const float*)d_in[2];
    const float* W_eq  = (const float*)d_in[3];
    const float* b_eq  = (const float*)d_in[4];
    const float* W_tr  = (const float*)d_in[5];
    const float* b_tr  = (const float*)d_in[6];
    const float* W_ab  = (const float*)d_in[7];
    const float* b_ab  = (const float*)d_in[8];
    const float* alpha = (const float*)d_in[9];
    const float* W1    = (const float*)d_in[10];
    const float* b1    = (const float*)d_in[11];
    const float* W2    = (const float*)d_in[12];
    const float* b2    = (const float*)d_in[13];
    float* out = (float*)d_out;

    float *gb = nullptr, *lb = nullptr;
    cudaGetSymbolAddress((void**)&gb, g_bufs);
    cudaGetSymbolAddress((void**)&lb, l_bufs);
    auto G = [&](int i) { return gb + (size_t)i * BATCH * DG; };
    auto L = [&](int i) { return lb + (size_t)i * BATCH * DG; };

    cudaFuncSetAttribute(plate_hmma<true>,  cudaFuncAttributeMaxDynamicSharedMemorySize, SMEM_TOTAL);
    cudaFuncSetAttribute(plate_hmma<false>, cudaFuncAttributeMaxDynamicSharedMemorySize, SMEM_TOTAL);
    cudaFuncSetAttribute(encoder_hmma,      cudaFuncAttributeMaxDynamicSharedMemorySize, SMEM_TOTAL);
    cudaFuncSetAttribute(head_hmma,         cudaFuncAttributeMaxDynamicSharedMemorySize, SMEM_TOTAL);

    cudaMemsetAsync(L(9), 0, (size_t)BATCH * DG * sizeof(float));
    prep_kernel<<<512, 256>>>(W_ge, W_eq, W_tr, W_ab, W1, W2);

    dim3 grid(BATCH / MTILE);   // 256 CTAs, 2 CTAs/SM

    encoder_hmma<<<grid, NTHREADS, SMEM_TOTAL>>>(x, b_ge, G(0));

    // Sweep 1: descending (g[1..8] None -> g_in = g0)
    for (int n = 8; n >= 1; --n)
        plate_hmma<true><<<grid, NTHREADS, SMEM_TOTAL>>>(G(0), L(n + 1), L(n),
                                                         b_eq, b_tr, b_ab, alpha);
    // Sweep 1: ascending
    for (int n = 1; n <= 8; ++n)
        plate_hmma<false><<<grid, NTHREADS, SMEM_TOTAL>>>(G(n - 1), L(n), G(n),
                                                          b_eq, b_tr, b_ab, alpha);
    // Sweep 2: descending
    for (int n = 8; n >= 1; --n)
        plate_hmma<true><<<grid, NTHREADS, SMEM_TOTAL>>>(G(n - 1), L(n + 1), L(n),
                                                         b_eq, b_tr, b_ab, alpha);
    // Sweep 2: ascending
    for (int n = 1; n <= 8; ++n)
        plate_hmma<false><<<grid, NTHREADS, SMEM_TOTAL>>>(G(n - 1), L(n), G(n),
                                                          b_eq, b_tr, b_ab, alpha);

    head_hmma<<<grid, NTHREADS, SMEM_TOTAL>>>(G(8), L(1), b1, b2, out);
}